// round 17
// baseline (speedup 1.0000x reference)
#include <cuda_runtime.h>
#include <cuda_bf16.h>
#include <cuda_fp16.h>
#include <math.h>
#include <stdint.h>

#define BB_ 4
#define SS_ 2048
#define DD_ 1024
#define HH_ 16
#define DH_ 64
#define NQKV ((size_t)BB_ * HH_ * SS_ * DH_)

// ---------------- scratch (device globals: allocation-free) ----------------
__device__ float g_att[(size_t)BB_ * SS_ * DD_];            // merged-head attn out
__device__ float g_wt[(size_t)3072 * 1024 + 1024 * 1024];   // W_in^T, W_out^T
// split operands (written by projection epilogue)
__device__ __align__(16) __nv_bfloat16 g_qh[NQKV], g_ql[NQKV];   // [bh][s][d]
__device__ __align__(16) __nv_bfloat16 g_kh[NQKV], g_kl[NQKV];   // [bh][s][d]
__device__ __align__(16) __half       g_vh[NQKV], g_vl[NQKV];    // [bh][d][s] (transposed)

// =============================== PTX helpers ===============================
__device__ __forceinline__ uint32_t smem_u32(const void* p) {
    uint32_t a;
    asm("{ .reg .u64 t; cvta.to.shared.u64 t, %1; cvt.u32.u64 %0, t; }"
        : "=r"(a) : "l"(p));
    return a;
}

__device__ __forceinline__ uint32_t f2tf(float x) {
    uint32_t r;
    asm("cvt.rna.tf32.f32 %0, %1;" : "=r"(r) : "f"(x));
    return r;
}

// pack two floats into bf16x2: low half = x0, high half = x1
__device__ __forceinline__ uint32_t pack2bf(float x0, float x1) {
    uint32_t r;
    asm("cvt.rn.bf16x2.f32 %0, %1, %2;" : "=r"(r) : "f"(x1), "f"(x0));
    return r;
}
// hi/lo split of a float pair into packed bf16x2
__device__ __forceinline__ void split2(float x0, float x1, uint32_t& ph, uint32_t& pl) {
    ph = pack2bf(x0, x1);
    float h0 = __uint_as_float(ph << 16);
    float h1 = __uint_as_float(ph & 0xffff0000u);
    pl = pack2bf(x0 - h0, x1 - h1);
}

#define MMA_TF32(c0,c1,c2,c3, a0,a1,a2,a3, b0,b1) \
    asm volatile( \
        "mma.sync.aligned.m16n8k8.row.col.f32.tf32.tf32.f32 " \
        "{%0,%1,%2,%3}, {%4,%5,%6,%7}, {%8,%9}, {%0,%1,%2,%3};" \
        : "+f"(c0), "+f"(c1), "+f"(c2), "+f"(c3) \
        : "r"(a0), "r"(a1), "r"(a2), "r"(a3), "r"(b0), "r"(b1))

#define MMA_BF16(c0,c1,c2,c3, a0,a1,a2,a3, b0,b1) \
    asm volatile( \
        "mma.sync.aligned.m16n8k16.row.col.f32.bf16.bf16.f32 " \
        "{%0,%1,%2,%3}, {%4,%5,%6,%7}, {%8,%9}, {%0,%1,%2,%3};" \
        : "+f"(c0), "+f"(c1), "+f"(c2), "+f"(c3) \
        : "r"(a0), "r"(a1), "r"(a2), "r"(a3), "r"(b0), "r"(b1))

#define MMA_F16(c0,c1,c2,c3, a0,a1,a2,a3, b0,b1) \
    asm volatile( \
        "mma.sync.aligned.m16n8k16.row.col.f32.f16.f16.f32 " \
        "{%0,%1,%2,%3}, {%4,%5,%6,%7}, {%8,%9}, {%0,%1,%2,%3};" \
        : "+f"(c0), "+f"(c1), "+f"(c2), "+f"(c3) \
        : "r"(a0), "r"(a1), "r"(a2), "r"(a3), "r"(b0), "r"(b1))

// ============================================================================
// W transpose: Wt[n*1024 + k] = W[k*N + n]
// ============================================================================
__global__ void transpose_kernel(const float* __restrict__ W, int N, int out_off)
{
    __shared__ float tile[32][33];
    int n0 = blockIdx.x * 32, k0 = blockIdx.y * 32;
    int tx = threadIdx.x, ty = threadIdx.y;   // 32 x 8
#pragma unroll
    for (int i = 0; i < 32; i += 8)
        tile[ty + i][tx] = W[(size_t)(k0 + ty + i) * N + n0 + tx];
    __syncthreads();
    float* Wt = g_wt + out_off;
#pragma unroll
    for (int i = 0; i < 32; i += 8)
        Wt[(size_t)(n0 + ty + i) * 1024 + k0 + tx] = tile[tx][ty + i];
}

// ============================================================================
// TF32 mma.sync GEMM: C[M,N] = A[M,1024] @ W[1024,N] + b
// mode 0: epilogue writes bf16 hi/lo Q/K (row layout) and fp16 hi/lo V (transposed)
// mode 1: A := g_att, dense fp32 out
// ============================================================================
#define ASTR 36
#define TILEF (128 * ASTR)
#define GSTAGES 3
#define GSMEM_BYTES (GSTAGES * 2 * TILEF * 4)   // 110,592

__device__ __forceinline__ void ld_tile(const float* __restrict__ src, int row0,
                                        int k0, float* dst, int t)
{
#pragma unroll
    for (int i = 0; i < 4; i++) {
        int idx = t + i * 256;
        int r = idx >> 3, c = idx & 7;
        const float* g = src + (size_t)(row0 + r) * 1024 + k0 + c * 4;
        uint32_t d = smem_u32(dst + r * ASTR + c * 4);
        asm volatile("cp.async.cg.shared.global [%0], [%1], 16;\n"
                     :: "r"(d), "l"(g));
    }
}

__global__ __launch_bounds__(256)
void mma_gemm(const float* __restrict__ A_, int wt_off,
              const float* __restrict__ bias, float* __restrict__ Cout,
              int Ntot, int mode)
{
    extern __shared__ __align__(16) float sm[];
    const float* A  = (mode == 1) ? g_att : A_;
    const float* Bt = g_wt + wt_off;
    float* As = sm;
    float* Bs = sm + GSTAGES * TILEF;

    const int t = threadIdx.x, wid = t >> 5, lane = t & 31;
    const int n0 = blockIdx.x * 128, m0 = blockIdx.y * 128;
    const int wm0 = (wid >> 2) * 64, wn0 = (wid & 3) * 32;
    const int ly = lane >> 2, lx = lane & 3;

    float c[4][4][4];
#pragma unroll
    for (int mf = 0; mf < 4; mf++)
#pragma unroll
        for (int nf = 0; nf < 4; nf++)
#pragma unroll
            for (int i = 0; i < 4; i++) c[mf][nf][i] = 0.f;

#pragma unroll
    for (int j = 0; j < 2; j++) {
        ld_tile(A,  m0, j * 32, As + j * TILEF, t);
        ld_tile(Bt, n0, j * 32, Bs + j * TILEF, t);
        asm volatile("cp.async.commit_group;\n" ::: "memory");
    }

    for (int kt = 0; kt < 32; kt++) {
        asm volatile("cp.async.wait_group 1;\n" ::: "memory");
        __syncthreads();

        int j = kt + 2;
        if (j < 32) {
            int s = j - (j / 3) * 3;
            ld_tile(A,  m0, j * 32, As + s * TILEF, t);
            ld_tile(Bt, n0, j * 32, Bs + s * TILEF, t);
        }
        asm volatile("cp.async.commit_group;\n" ::: "memory");

        const int scur = kt - (kt / 3) * 3;
        const float* Asb = As + scur * TILEF;
        const float* Bsb = Bs + scur * TILEF;

#pragma unroll
        for (int ks = 0; ks < 4; ks++) {
            const int k0 = ks * 8;
            uint32_t af[4][4], bf[4][2];
#pragma unroll
            for (int mf = 0; mf < 4; mf++) {
                const float* ab = Asb + (wm0 + mf * 16 + ly) * ASTR + k0 + lx;
                af[mf][0] = f2tf(ab[0]);
                af[mf][1] = f2tf(ab[8 * ASTR]);
                af[mf][2] = f2tf(ab[4]);
                af[mf][3] = f2tf(ab[8 * ASTR + 4]);
            }
#pragma unroll
            for (int nf = 0; nf < 4; nf++) {
                const float* bb = Bsb + (wn0 + nf * 8 + ly) * ASTR + k0 + lx;
                bf[nf][0] = f2tf(bb[0]);
                bf[nf][1] = f2tf(bb[4]);
            }
#pragma unroll
            for (int mf = 0; mf < 4; mf++)
#pragma unroll
                for (int nf = 0; nf < 4; nf++)
                    MMA_TF32(c[mf][nf][0], c[mf][nf][1], c[mf][nf][2], c[mf][nf][3],
                             af[mf][0], af[mf][1], af[mf][2], af[mf][3],
                             bf[nf][0], bf[nf][1]);
        }
    }
    asm volatile("cp.async.wait_group 0;\n" ::: "memory");

#pragma unroll
    for (int mf = 0; mf < 4; mf++) {
        const int r0 = m0 + wm0 + mf * 16 + ly;
#pragma unroll
        for (int nf = 0; nf < 4; nf++) {
            const int cb = n0 + wn0 + nf * 8 + lx * 2;
            float2 bv = *(const float2*)&bias[cb];
            float2 v0 = make_float2(c[mf][nf][0] + bv.x, c[mf][nf][1] + bv.y);
            float2 v1 = make_float2(c[mf][nf][2] + bv.x, c[mf][nf][3] + bv.y);
            if (mode == 0) {
                const int sec = cb >> 10;
                const int h   = (cb & 1023) >> 6;
                const int dh0 = cb & 63;
                const int bb0 = r0 >> 11, ss0 = r0 & 2047;
                const int bb1 = (r0 + 8) >> 11, ss1 = (r0 + 8) & 2047;
                const size_t bhh0 = (size_t)(bb0 * HH_ + h);
                const size_t bhh1 = (size_t)(bb1 * HH_ + h);
                if (sec < 2) {
                    __nv_bfloat16* dh = (sec == 0) ? g_qh : g_kh;
                    __nv_bfloat16* dl = (sec == 0) ? g_ql : g_kl;
                    uint32_t ph, pl;
                    split2(v0.x, v0.y, ph, pl);
                    size_t i0 = (bhh0 * SS_ + ss0) * DH_ + dh0;
                    *(uint32_t*)&dh[i0] = ph;  *(uint32_t*)&dl[i0] = pl;
                    split2(v1.x, v1.y, ph, pl);
                    size_t i1 = (bhh1 * SS_ + ss1) * DH_ + dh0;
                    *(uint32_t*)&dh[i1] = ph;  *(uint32_t*)&dl[i1] = pl;
                } else {
                    // V transposed [d][key], fp16 hi/lo
                    size_t vb0 = bhh0 * DH_, vb1 = bhh1 * DH_;
                    __half hx, hy;
                    hx = __float2half_rn(v0.x);
                    hy = __float2half_rn(v0.y);
                    g_vh[(vb0 + dh0)     * SS_ + ss0] = hx;
                    g_vh[(vb0 + dh0 + 1) * SS_ + ss0] = hy;
                    g_vl[(vb0 + dh0)     * SS_ + ss0] = __float2half_rn(v0.x - __half2float(hx));
                    g_vl[(vb0 + dh0 + 1) * SS_ + ss0] = __float2half_rn(v0.y - __half2float(hy));
                    hx = __float2half_rn(v1.x);
                    hy = __float2half_rn(v1.y);
                    g_vh[(vb1 + dh0)     * SS_ + ss1] = hx;
                    g_vh[(vb1 + dh0 + 1) * SS_ + ss1] = hy;
                    g_vl[(vb1 + dh0)     * SS_ + ss1] = __float2half_rn(v1.x - __half2float(hx));
                    g_vl[(vb1 + dh0 + 1) * SS_ + ss1] = __float2half_rn(v1.y - __half2float(hy));
                }
            } else {
                *(float2*)&Cout[(size_t)r0 * Ntot + cb] = v0;
                *(float2*)&Cout[(size_t)(r0 + 8) * Ntot + cb] = v1;
            }
        }
    }
}

// ============================================================================
// Fused attention, 512 threads (16 warps) per block = (b, h, 16-query tile).
//   Warp-private 3-stage K/V pipelines (prefetch distance 2), no block syncs
//   in the hot loops. Scores: bf16-pair m16n8k16 (3 terms). P stored in smem
//   as fp16 -> PV A-frags are direct LDS (no split), PV = fp16 2-term mma.
// ============================================================================
#define TKEY 128
#define PSWH 2056                       // P row stride in halfs (bank-clean)
#define QSTR 72
// per-warp K slice: 8 keys x 72 bf16 x 2 comps = 1152 bf16/stage; 3 stages
#define KW_STAGE 1152
#define KW_STRIDE (3 * KW_STAGE)        // 3456 half-words per warp
// per-warp V slice: 2 comps x 32 d x 24 (16 keys + pad) = 1536 halfs/stage; 3 stages
#define VW_STAGE 1536
#define VW_STRIDE (3 * VW_STAGE)        // 4608 halfs per warp
#define VCOMP_H 768                     // 32 d x 24
#define KVFLOATS 36864                  // region = 16 warps x 4608 halfs = 147,456 B
// floats: PsH 16448 + KV 36864 + Qs 1152 + red 256 + inv 16
#define ATTN_SMEM_FLOATS (16448 + KVFLOATS + 1152 + 256 + 16)
#define ATTN_SMEM_BYTES  (ATTN_SMEM_FLOATS * 4)   // 218,944

// Warp-private K slice: keys [key0,key0+8), 64 d, hi+lo bf16.
__device__ __forceinline__ void ld_kslice(const __nv_bfloat16* __restrict__ kh,
                                          const __nv_bfloat16* __restrict__ kl,
                                          int key0, __nv_bfloat16* dst, int lane)
{
#pragma unroll
    for (int i = 0; i < 4; i++) {
        int idx = lane + i * 32;
        int comp = idx >> 6, rem = idx & 63;
        int r = rem >> 3, c = rem & 7;
        const __nv_bfloat16* g = (comp ? kl : kh) + (size_t)(key0 + r) * DH_ + c * 8;
        uint32_t d = smem_u32(dst + comp * 576 + r * 72 + c * 8);
        asm volatile("cp.async.cg.shared.global [%0], [%1], 16;\n"
                     :: "r"(d), "l"(g));
    }
}

// Warp-private V slice: d [dhalf,dhalf+32), keys [key0,key0+16), hi+lo fp16,
// row stride 24 halfs (bank-clean B-fragments).
__device__ __forceinline__ void ld_vslice(const __half* __restrict__ vh,
                                          const __half* __restrict__ vl,
                                          int key0, int dhalf,
                                          __half* dst, int lane)
{
#pragma unroll
    for (int i = 0; i < 4; i++) {
        int idx = lane + i * 32;
        int comp = idx >> 6, rem = idx & 63;
        int d = rem >> 1, c = rem & 1;
        const __half* g = (comp ? vl : vh) + (size_t)(dhalf + d) * SS_ + key0 + c * 8;
        uint32_t dd = smem_u32(dst + comp * VCOMP_H + d * 24 + c * 8);
        asm volatile("cp.async.cg.shared.global [%0], [%1], 16;\n"
                     :: "r"(dd), "l"(g));
    }
}

__global__ __launch_bounds__(512, 1)
void attn_kernel(const float* __restrict__ amask, float* __restrict__ attw)
{
    extern __shared__ __align__(16) float sm[];
    __half* PsH = (__half*)sm;                        // 16 x PSWH fp16
    float* KVf  = sm + 16448;                         // warp-private staging
    __nv_bfloat16* KVbf = (__nv_bfloat16*)KVf;
    __half*        KVh  = (__half*)KVf;
    __nv_bfloat16* Qsbf = (__nv_bfloat16*)(KVf + KVFLOATS);   // 2 x 16 x QSTR
    float* red = KVf + KVFLOATS + 1152;
    float* inv = red + 256;

    const int t  = threadIdx.x;
    const int qt = blockIdx.x, h = blockIdx.y, b = blockIdx.z;
    const int q0 = qt * 16;
    const size_t bh = (size_t)(b * HH_ + h);
    const __nv_bfloat16* Qh = g_qh + bh * SS_ * DH_;
    const __nv_bfloat16* Ql = g_ql + bh * SS_ * DH_;
    const __nv_bfloat16* Kh = g_kh + bh * SS_ * DH_;
    const __nv_bfloat16* Kl = g_kl + bh * SS_ * DH_;
    const __half* Vh = g_vh + bh * DH_ * SS_;
    const __half* Vl = g_vl + bh * DH_ * SS_;

    const int w = t >> 5, lane = t & 31;
    const int ly = lane >> 2, lx = lane & 3;

    // ---- load Q tile [2 comp][16][64] bf16 ----
    if (t < 256) {
        int comp = t >> 7, rem = t & 127, r = rem >> 3, c = rem & 7;
        const __nv_bfloat16* g = (comp ? Ql : Qh) + (size_t)(q0 + r) * DH_ + c * 8;
        *(uint4*)&Qsbf[comp * 16 * QSTR + r * QSTR + c * 8] = *(const uint4*)g;
    }

    const int num_kt = q0 / TKEY + 1;
    __nv_bfloat16* Kw = KVbf + w * KW_STRIDE;

    // ---- prologue: K tiles 0 and 1 (3-stage ring, distance 2) ----
    ld_kslice(Kh, Kl, w * 8, Kw, lane);
    asm volatile("cp.async.commit_group;\n" ::: "memory");
    if (num_kt > 1) {
        ld_kslice(Kh, Kl, TKEY + w * 8, Kw + KW_STAGE, lane);
        asm volatile("cp.async.commit_group;\n" ::: "memory");
    }
    __syncthreads();   // Qs visible to all warps

    // ---- hoist Q a-fragments (packed bf16x2) ----
    uint32_t qah[4][4], qal[4][4];
    {
        const __nv_bfloat16* Qsh = Qsbf;
        const __nv_bfloat16* Qsl = Qsbf + 16 * QSTR;
#pragma unroll
        for (int ks = 0; ks < 4; ks++) {
            int o = ks * 16 + 2 * lx;
            qah[ks][0] = *(const uint32_t*)&Qsh[ly * QSTR + o];
            qah[ks][1] = *(const uint32_t*)&Qsh[(ly + 8) * QSTR + o];
            qah[ks][2] = *(const uint32_t*)&Qsh[ly * QSTR + o + 8];
            qah[ks][3] = *(const uint32_t*)&Qsh[(ly + 8) * QSTR + o + 8];
            qal[ks][0] = *(const uint32_t*)&Qsl[ly * QSTR + o];
            qal[ks][1] = *(const uint32_t*)&Qsl[(ly + 8) * QSTR + o];
            qal[ks][2] = *(const uint32_t*)&Qsl[ly * QSTR + o + 8];
            qal[ks][3] = *(const uint32_t*)&Qsl[(ly + 8) * QSTR + o + 8];
        }
    }

    float rsum0 = 0.f, rsum1 = 0.f;

    // =================== score phase (no block syncs) ===================
    for (int kt = 0; kt < num_kt; kt++) {
        const int j0 = kt * TKEY;
        if (kt + 2 < num_kt) {
            int s2 = (kt + 2) - ((kt + 2) / 3) * 3;
            ld_kslice(Kh, Kl, j0 + 2 * TKEY + w * 8, Kw + s2 * KW_STAGE, lane);
            asm volatile("cp.async.commit_group;\n" ::: "memory");
            asm volatile("cp.async.wait_group 2;\n" ::: "memory");
        } else if (kt + 1 < num_kt) {
            asm volatile("cp.async.wait_group 1;\n" ::: "memory");
        } else {
            asm volatile("cp.async.wait_group 0;\n" ::: "memory");
        }
        __syncwarp();

        const int scur = kt - (kt / 3) * 3;
        const __nv_bfloat16* Kbh = Kw + scur * KW_STAGE;
        const __nv_bfloat16* Kbl = Kbh + 576;
        float c0 = 0.f, c1 = 0.f, c2 = 0.f, c3 = 0.f;
        const int krow = ly * 72;

#pragma unroll
        for (int ks = 0; ks < 4; ks++) {
            int o = ks * 16 + 2 * lx;
            uint32_t bh0 = *(const uint32_t*)&Kbh[krow + o];
            uint32_t bh1 = *(const uint32_t*)&Kbh[krow + o + 8];
            uint32_t bl0 = *(const uint32_t*)&Kbl[krow + o];
            uint32_t bl1 = *(const uint32_t*)&Kbl[krow + o + 8];
            MMA_BF16(c0, c1, c2, c3, qah[ks][0], qah[ks][1], qah[ks][2], qah[ks][3], bh0, bh1);
            MMA_BF16(c0, c1, c2, c3, qah[ks][0], qah[ks][1], qah[ks][2], qah[ks][3], bl0, bl1);
            MMA_BF16(c0, c1, c2, c3, qal[ks][0], qal[ks][1], qal[ks][2], qal[ks][3], bh0, bh1);
        }

        const int col = j0 + w * 8 + 2 * lx;
        const float am0 = amask[b * SS_ + col];
        const float am1 = amask[b * SS_ + col + 1];
        const int qg0 = q0 + ly, qg1 = q0 + ly + 8;
        float e0 = (col     <= qg0) ? __expf(c0 * 0.125f + am0) : 0.f;
        float e1 = (col + 1 <= qg0) ? __expf(c1 * 0.125f + am1) : 0.f;
        float e2 = (col     <= qg1) ? __expf(c2 * 0.125f + am0) : 0.f;
        float e3 = (col + 1 <= qg1) ? __expf(c3 * 0.125f + am1) : 0.f;
        rsum0 += e0 + e1;
        rsum1 += e2 + e3;
        *(__half2*)&PsH[ly * PSWH + col]       = __floats2half2_rn(e0, e1);
        *(__half2*)&PsH[(ly + 8) * PSWH + col] = __floats2half2_rn(e2, e3);
        // no block sync: buffers are warp-private
    }

    // ---- row sums -> red; barrier fences K-region reuse by V ----
    rsum0 += __shfl_xor_sync(0xffffffffu, rsum0, 1);
    rsum0 += __shfl_xor_sync(0xffffffffu, rsum0, 2);
    rsum1 += __shfl_xor_sync(0xffffffffu, rsum1, 1);
    rsum1 += __shfl_xor_sync(0xffffffffu, rsum1, 2);
    if (lx == 0) {
        red[ly * 16 + w]       = rsum0;
        red[(ly + 8) * 16 + w] = rsum1;
    }
    __syncthreads();   // all warps done with score phase + K buffers + Ps writes

    // ---- V tiles 0,1 prologue (warp-private; K region now safe to reuse) ----
    const int s8 = w & 7;
    const int dhalf = (w >> 3) * 32;
    __half* Vw = KVh + w * VW_STRIDE;
    ld_vslice(Vh, Vl, 16 * s8, dhalf, Vw, lane);
    asm volatile("cp.async.commit_group;\n" ::: "memory");
    if (num_kt > 1) {
        ld_vslice(Vh, Vl, TKEY + 16 * s8, dhalf, Vw + VW_STAGE, lane);
        asm volatile("cp.async.commit_group;\n" ::: "memory");
    }

    // ---- finish rowsum reduction -> inv[r] ----
    if (t < 256) {
        int r = t >> 4, x = t & 15;
        float s = red[r * 16 + x];
        s += __shfl_down_sync(0xffffffffu, s, 8, 16);
        s += __shfl_down_sync(0xffffffffu, s, 4, 16);
        s += __shfl_down_sync(0xffffffffu, s, 2, 16);
        s += __shfl_down_sync(0xffffffffu, s, 1, 16);
        if (x == 0) inv[r] = 1.0f / s;
    }
    __syncthreads();

    // ---- write normalized P (overlaps V prologue latency) ----
    {
        int r = t >> 5, x = t & 31;
        float invr = inv[r];
        float* orow = attw + ((bh * SS_) + q0 + r) * (size_t)SS_;
        const int JMAX = num_kt * TKEY;
#pragma unroll 4
        for (int it = 0; it < 16; it++) {
            int col = it * 128 + x * 4;
            float4 v;
            if (col < JMAX) {
                float2 f0 = __half22float2(*(const __half2*)&PsH[r * PSWH + col]);
                float2 f1 = __half22float2(*(const __half2*)&PsH[r * PSWH + col + 2]);
                v = make_float4(f0.x * invr, f0.y * invr, f1.x * invr, f1.y * invr);
            } else {
                v = make_float4(0.f, 0.f, 0.f, 0.f);
            }
            *(float4*)&orow[col] = v;
        }
    }

    // =================== PV phase (fp16 2-term mma, no block syncs) =========
    {
        float acc[4][4];
#pragma unroll
        for (int nf = 0; nf < 4; nf++)
#pragma unroll
            for (int i = 0; i < 4; i++) acc[nf][i] = 0.f;

        for (int kt2 = 0; kt2 < num_kt; kt2++) {
            if (kt2 + 2 < num_kt) {
                int s2 = (kt2 + 2) - ((kt2 + 2) / 3) * 3;
                ld_vslice(Vh, Vl, (kt2 + 2) * TKEY + 16 * s8, dhalf,
                          Vw + s2 * VW_STAGE, lane);
                asm volatile("cp.async.commit_group;\n" ::: "memory");
                asm volatile("cp.async.wait_group 2;\n" ::: "memory");
            } else if (kt2 + 1 < num_kt) {
                asm volatile("cp.async.wait_group 1;\n" ::: "memory");
            } else {
                asm volatile("cp.async.wait_group 0;\n" ::: "memory");
            }
            __syncwarp();

            const int scur = kt2 - (kt2 / 3) * 3;
            const __half* Vbh = Vw + scur * VW_STAGE;
            const __half* Vbl = Vbh + VCOMP_H;
            const int j0w = kt2 * TKEY + s8 * 16;

            // A-frag: P fp16 DIRECT loads (no split)
            uint32_t pa0 = *(const uint32_t*)&PsH[ly * PSWH + j0w + 2 * lx];
            uint32_t pa1 = *(const uint32_t*)&PsH[(ly + 8) * PSWH + j0w + 2 * lx];
            uint32_t pa2 = *(const uint32_t*)&PsH[ly * PSWH + j0w + 2 * lx + 8];
            uint32_t pa3 = *(const uint32_t*)&PsH[(ly + 8) * PSWH + j0w + 2 * lx + 8];

#pragma unroll
            for (int nf = 0; nf < 4; nf++) {
                const int drow = (nf * 8 + ly) * 24 + 2 * lx;
                uint32_t vh0 = *(const uint32_t*)&Vbh[drow];
                uint32_t vh1 = *(const uint32_t*)&Vbh[drow + 8];
                uint32_t vl0 = *(const uint32_t*)&Vbl[drow];
                uint32_t vl1 = *(const uint32_t*)&Vbl[drow + 8];
                MMA_F16(acc[nf][0], acc[nf][1], acc[nf][2], acc[nf][3],
                        pa0, pa1, pa2, pa3, vh0, vh1);
                MMA_F16(acc[nf][0], acc[nf][1], acc[nf][2], acc[nf][3],
                        pa0, pa1, pa2, pa3, vl0, vl1);
            }
            // no block sync: V buffers are warp-private
        }
        __syncthreads();   // all warps done reading V region before rb reuse

        // ---- cross-warp reduce (8 partials per d-half) -> g_att ----
        float* rb = KVf;   // 16 warps x 16 rows x 34 = 8704 floats
#pragma unroll
        for (int nf = 0; nf < 4; nf++) {
            *(float2*)&rb[w * 544 + ly * 34 + nf * 8 + 2 * lx] =
                make_float2(acc[nf][0], acc[nf][1]);
            *(float2*)&rb[w * 544 + (ly + 8) * 34 + nf * 8 + 2 * lx] =
                make_float2(acc[nf][2], acc[nf][3]);
        }
        __syncthreads();
        {
            int r = t >> 5, c2 = (t & 31) * 2;
            int dh = c2 >> 5, loc = c2 & 31;
            float invr = inv[r];
            float2 s = make_float2(0.f, 0.f);
#pragma unroll
            for (int w2 = 0; w2 < 8; w2++) {
                float2 x2 = *(const float2*)&rb[(dh * 8 + w2) * 544 + r * 34 + loc];
                s.x += x2.x; s.y += x2.y;
            }
            s.x *= invr; s.y *= invr;
            *(float2*)&g_att[((size_t)(b * SS_) + q0 + r) * DD_ + h * 64 + c2] = s;
        }
    }
}

// ============================================================================
extern "C" void kernel_launch(void* const* d_in, const int* in_sizes, int n_in,
                              void* d_out, int out_size)
{
    (void)in_sizes; (void)n_in; (void)out_size;
    const float* x     = (const float*)d_in[0];
    const float* amask = (const float*)d_in[1];
    const float* W_in  = (const float*)d_in[2];
    const float* b_in  = (const float*)d_in[3];
    const float* W_out = (const float*)d_in[4];
    const float* b_out = (const float*)d_in[5];

    float* out  = (float*)d_out;
    float* attw = out + (size_t)BB_ * SS_ * DD_;   // tuple order: (out, attn_weights)

    cudaFuncSetAttribute(attn_kernel, cudaFuncAttributeMaxDynamicSharedMemorySize,
                         ATTN_SMEM_BYTES);
    cudaFuncSetAttribute(mma_gemm, cudaFuncAttributeMaxDynamicSharedMemorySize,
                         GSMEM_BYTES);

    // 0) transpose weights into K-major [N,K] scratch
    transpose_kernel<<<dim3(96, 32), dim3(32, 8)>>>(W_in, 3072, 0);
    transpose_kernel<<<dim3(32, 32), dim3(32, 8)>>>(W_out, 1024, 3072 * 1024);

    // 1) QKV projection -> bf16 hi/lo Q/K, fp16 hi/lo V (transposed)
    mma_gemm<<<dim3(24, 64), 256, GSMEM_BYTES>>>(x, 0, b_in, nullptr, 3072, 0);

    // 2) attention (warp-private 3-stage staging; fp16 P; 2-term PV)
    attn_kernel<<<dim3(SS_ / 16, HH_, BB_), 512, ATTN_SMEM_BYTES>>>(amask, attw);

    // 3) output projection -> d_out head
    mma_gemm<<<dim3(8, 64), 256, GSMEM_BYTES>>>(nullptr, 3072 * 1024, b_out, out, 1024, 1);
}